// round 12
// baseline (speedup 1.0000x reference)
#include <cuda_runtime.h>
#include <cuda_fp16.h>
#include <cstdint>

// ---------------- problem constants ----------------
#define M_TOT 2048
#define K_DIM 256
#define N_LUT 5532
#define N_CQ  5000
#define N_TOT 10788
#define N_PAD 11008            // 43 * 256 (zero-padded B rows); >= 17*640=10880
#define SCALE 30.0f

// ---------------- GEMM tiling ----------------
#define BM 128
#define BN 128
#define TILES 5                // N-tiles per CTA (walk along N, A resident)
#define KCHUNK 4               // K chunks of 64 per tile (K = 256)
#define TOTAL_CHUNKS (TILES * KCHUNK)   // 20
#define A_BYTES 65536          // 4 chunks x 16KB: full 128x256 A tile
#define B_STAGE 16384          // one B chunk: 128 rows x 128B
#define STAGES 3
#define SMEM_BYTES (1024 + A_BYTES + STAGES * B_STAGE)   // 115712 -> 2 CTAs/SM
#define NTHREADS 256

typedef unsigned int u32;

// ---------------- device scratch (no allocs allowed) ----------------
__device__ __align__(1024) __half g_A[(size_t)M_TOT * K_DIM];   // 1 MB   (pre-scaled by 30)
__device__ __align__(1024) __half g_B[(size_t)N_PAD * K_DIM];   // 5.6 MB

// ---------------- PTX helpers (plain sm_80+ features only) ----------------
static __device__ __forceinline__ u32 cvta_smem(const void* p) {
    u32 a;
    asm("{ .reg .u64 t; cvta.to.shared.u64 t, %1; cvt.u32.u64 %0, t; }" : "=r"(a) : "l"(p));
    return a;
}

static __device__ __forceinline__ void cp_async16(u32 dst, const void* src) {
    asm volatile("cp.async.cg.shared.global [%0], [%1], 16;" :: "r"(dst), "l"(src) : "memory");
}

static __device__ __forceinline__ void ldmatrix4(u32* f, u32 addr) {
    asm volatile("ldmatrix.sync.aligned.m8n8.x4.shared.b16 {%0,%1,%2,%3}, [%4];"
                 : "=r"(f[0]), "=r"(f[1]), "=r"(f[2]), "=r"(f[3]) : "r"(addr));
}

static __device__ __forceinline__ void mma_fp16(float* c, const u32* a, const u32* b) {
    asm volatile(
        "mma.sync.aligned.m16n8k16.row.col.f32.f16.f16.f32 "
        "{%0,%1,%2,%3}, {%4,%5,%6,%7}, {%8,%9}, {%0,%1,%2,%3};"
        : "+f"(c[0]), "+f"(c[1]), "+f"(c[2]), "+f"(c[3])
        : "r"(a[0]), "r"(a[1]), "r"(a[2]), "r"(a[3]), "r"(b[0]), "r"(b[1]));
}

// ---------------- pack kernel: fp32 -> fp16 (A pre-scaled by 30) ----------------
__global__ void pack_kernel(const float* __restrict__ A, const float* __restrict__ lut,
                            const float* __restrict__ cq, const float* __restrict__ nonid)
{
    const int t = threadIdx.x;
    const int row = blockIdx.x * 4 + (t >> 6);     // 4 rows per block
    const int k0 = (t & 63) * 4;

    const float* src;
    __half* dst;
    float mul = 1.0f;
    if (row < M_TOT) {
        src = A + (size_t)row * K_DIM;
        dst = g_A + (size_t)row * K_DIM;
        mul = SCALE;
    } else {
        const int n = row - M_TOT;
        dst = g_B + (size_t)n * K_DIM;
        if (n < N_LUT)              src = lut   + (size_t)n * K_DIM;
        else if (n < N_LUT + N_CQ)  src = cq    + (size_t)(n - N_LUT) * K_DIM;
        else if (n < N_TOT)         src = nonid + (size_t)(n - N_LUT - N_CQ) * K_DIM;
        else                        src = nullptr;   // zero padding rows
    }

    float4 v = src ? *reinterpret_cast<const float4*>(src + k0)
                   : make_float4(0.f, 0.f, 0.f, 0.f);

    unsigned short h[4];
    h[0] = __half_as_ushort(__float2half_rn(v.x * mul));
    h[1] = __half_as_ushort(__float2half_rn(v.y * mul));
    h[2] = __half_as_ushort(__float2half_rn(v.z * mul));
    h[3] = __half_as_ushort(__float2half_rn(v.w * mul));
    uint2 p;
    p.x = ((u32)h[1] << 16) | h[0];
    p.y = ((u32)h[3] << 16) | h[2];
    *reinterpret_cast<uint2*>(dst + k0) = p;
}

// ---------------- main GEMM: resident A, 5 B-tiles streamed per CTA ----------------
__global__ void __launch_bounds__(NTHREADS, 2)
oim_mma_gemm(float* __restrict__ out)
{
    extern __shared__ char smem_raw[];
    u32 base = cvta_smem(smem_raw);
    base = (base + 1023u) & ~1023u;        // 1024-align tile region
    const u32 bbase = base + A_BYTES;

    const int tid = threadIdx.x;
    const int lid = tid & 31;
    const int wid = tid >> 5;
    const int wm  = wid & 1;               // 2 warps in M
    const int wn  = wid >> 1;              // 4 warps in N

    const int m0     = blockIdx.y * BM;
    const int n_base = blockIdx.x * (TILES * BN);

    // ---- producer mapping: each thread copies 4 B (+4 A while c<4) 16B segments
    const int r0  = tid >> 3;              // 0..31
    const int seg = tid & 7;               // 16B segment within 128B row

    // ---- ldmatrix lane constants
    const int mat = lid >> 3, rr = lid & 7;
    const int a_row = wm * 64 + ((mat & 1) << 3) + rr;   // + mi*16
    const u32 a_xor = (u32)(a_row & 7);
    const int a_ck  = mat >> 1;                           // 16B chunk within k16
    const int b_row = wn * 32 + ((mat >> 1) << 3) + rr;   // + p*16
    const u32 b_xor = (u32)(b_row & 7);
    const int b_ck  = mat & 1;

    float acc[4][4][4];
    #pragma unroll
    for (int i = 0; i < 4; i++)
        #pragma unroll
        for (int j = 0; j < 4; j++)
            #pragma unroll
            for (int v = 0; v < 4; v++)
                acc[i][j][v] = 0.f;

    // global chunk c: tile = c/4 (B col group), k = c%4 (K columns [k*64, k*64+64))
    auto issue_group = [&](int c) {
        const int k    = c & 3;
        const int tile = c >> 2;
        const int koff = k << 6;
        const u32 bstage = bbase + (u32)(c % STAGES) * B_STAGE;
        const __half* bsrc = g_B + (size_t)(n_base + tile * BN + r0) * K_DIM + koff + seg * 8;
        #pragma unroll
        for (int j = 0; j < 4; ++j) {
            const u32 rel = (u32)((r0 + j * 32) * 128 + seg * 16);
            const u32 sw  = rel ^ ((rel >> 3) & 0x70u);
            cp_async16(bstage + sw, bsrc + (size_t)j * 32 * K_DIM);
        }
        if (c < KCHUNK) {   // A chunk k, loaded once, resident for all tiles
            const u32 astage = base + (u32)k * 16384u;
            const __half* asrc = g_A + (size_t)(m0 + r0) * K_DIM + koff + seg * 8;
            #pragma unroll
            for (int j = 0; j < 4; ++j) {
                const u32 rel = (u32)((r0 + j * 32) * 128 + seg * 16);
                const u32 sw  = rel ^ ((rel >> 3) & 0x70u);
                cp_async16(astage + sw, asrc + (size_t)j * 32 * K_DIM);
            }
        }
        asm volatile("cp.async.commit_group;" ::: "memory");
    };

    issue_group(0);
    issue_group(1);

    for (int q = 0; q < TOTAL_CHUNKS; ++q) {
        if (q < TOTAL_CHUNKS - 1) asm volatile("cp.async.wait_group 1;" ::: "memory");
        else                      asm volatile("cp.async.wait_group 0;" ::: "memory");
        __syncthreads();   // group q resident; prior reads of recycled B stage done

        if (q + 2 < TOTAL_CHUNKS) issue_group(q + 2);

        const u32 sA = base + (u32)(q & 3) * 16384u;
        const u32 sB = bbase + (u32)(q % STAGES) * B_STAGE;

        #pragma unroll
        for (int ks = 0; ks < 4; ++ks) {
            u32 af[4][4];
            #pragma unroll
            for (int mi = 0; mi < 4; ++mi) {
                const u32 row  = (u32)(a_row + mi * 16);
                const u32 addr = sA + row * 128u + ((((u32)(ks * 2 + a_ck)) ^ a_xor) << 4);
                ldmatrix4(af[mi], addr);
            }
            u32 bf[4][2];
            #pragma unroll
            for (int p = 0; p < 2; ++p) {
                const u32 row  = (u32)(b_row + p * 16);
                const u32 addr = sB + row * 128u + ((((u32)(ks * 2 + b_ck)) ^ b_xor) << 4);
                u32 t[4];
                ldmatrix4(t, addr);
                bf[p * 2][0] = t[0];     bf[p * 2][1] = t[1];
                bf[p * 2 + 1][0] = t[2]; bf[p * 2 + 1][1] = t[3];
            }
            #pragma unroll
            for (int mi = 0; mi < 4; ++mi)
                #pragma unroll
                for (int ni = 0; ni < 4; ++ni)
                    mma_fp16(acc[mi][ni], af[mi], bf[ni]);
        }

        // ---- end of a tile: store it (overlaps next tile's cp.async), reset acc
        if ((q & 3) == 3) {
            const int tile = q >> 2;
            const int row_base = m0 + wm * 64 + (lid >> 2);
            const int col_base = n_base + tile * BN + wn * 32 + (lid & 3) * 2;
            #pragma unroll
            for (int mi = 0; mi < 4; ++mi) {
                const int r1 = row_base + mi * 16;
                float* o1 = out + (size_t)r1 * N_TOT;
                float* o2 = out + (size_t)(r1 + 8) * N_TOT;
                #pragma unroll
                for (int ni = 0; ni < 4; ++ni) {
                    const int col = col_base + ni * 8;
                    if (col < N_TOT) {
                        float2 v0, v1;
                        v0.x = acc[mi][ni][0];  v0.y = acc[mi][ni][1];
                        v1.x = acc[mi][ni][2];  v1.y = acc[mi][ni][3];
                        *reinterpret_cast<float2*>(o1 + col) = v0;
                        *reinterpret_cast<float2*>(o2 + col) = v1;
                    }
                }
            }
            #pragma unroll
            for (int i = 0; i < 4; i++)
                #pragma unroll
                for (int j = 0; j < 4; j++)
                    #pragma unroll
                    for (int v = 0; v < 4; v++)
                        acc[i][j][v] = 0.f;
        }
    }
}

// ---------------- launch ----------------
extern "C" void kernel_launch(void* const* d_in, const int* in_sizes, int n_in,
                              void* d_out, int out_size)
{
    // metadata order: inputs, non_id_feat, lut, cq, first_pos, second_pos, targets, half, header
    const float* inputs = (const float*)d_in[0];
    const float* nonid  = (const float*)d_in[1];
    const float* lut    = (const float*)d_in[2];
    const float* cq     = (const float*)d_in[3];
    float* out = (float*)d_out;

    pack_kernel<<<(M_TOT + N_PAD) / 4, 256>>>(inputs, lut, cq, nonid);

    cudaFuncSetAttribute(oim_mma_gemm, cudaFuncAttributeMaxDynamicSharedMemorySize, SMEM_BYTES);
    // 17 N-groups x 16 M-tiles = 272 CTAs -> single wave at 2 CTAs/SM
    dim3 grid(17, M_TOT / BM);
    oim_mma_gemm<<<grid, NTHREADS, SMEM_BYTES>>>(out);
}

// round 13
// speedup vs baseline: 1.6753x; 1.6753x over previous
#include <cuda_runtime.h>
#include <cuda_fp16.h>
#include <cstdint>

// ---------------- problem constants ----------------
#define M_TOT 2048
#define K_DIM 256
#define N_LUT 5532
#define N_CQ  5000
#define N_TOT 10788
#define N_PAD 11008            // 43 * 256 (zero-padded B rows)
#define SCALE 30.0f

// ---------------- GEMM tiling ----------------
#define BM 128
#define BN 128
#define NCHUNK 4               // 4 chunks of 64 fp16 = K 256
#define STAGES 3
#define STAGE_BYTES 32768      // A tile 16KB + B tile 16KB (128 rows x 128B)
#define SMEM_BYTES (1024 + STAGES * STAGE_BYTES)
#define NTHREADS 256

typedef unsigned int u32;

// ---------------- device scratch (no allocs allowed) ----------------
__device__ __align__(1024) __half g_A[(size_t)M_TOT * K_DIM];   // 1 MB  (pre-scaled by 30)
__device__ __align__(1024) __half g_B[(size_t)N_PAD * K_DIM];   // 5.6 MB

// ---------------- PTX helpers (plain sm_80+ features only) ----------------
static __device__ __forceinline__ u32 cvta_smem(const void* p) {
    u32 a;
    asm("{ .reg .u64 t; cvta.to.shared.u64 t, %1; cvt.u32.u64 %0, t; }" : "=r"(a) : "l"(p));
    return a;
}

static __device__ __forceinline__ void cp_async16(u32 dst, const void* src) {
    asm volatile("cp.async.cg.shared.global [%0], [%1], 16;" :: "r"(dst), "l"(src) : "memory");
}

static __device__ __forceinline__ void ldmatrix4(u32* f, u32 addr) {
    asm volatile("ldmatrix.sync.aligned.m8n8.x4.shared.b16 {%0,%1,%2,%3}, [%4];"
                 : "=r"(f[0]), "=r"(f[1]), "=r"(f[2]), "=r"(f[3]) : "r"(addr));
}

static __device__ __forceinline__ void mma_fp16(float* c, const u32* a, const u32* b) {
    asm volatile(
        "mma.sync.aligned.m16n8k16.row.col.f32.f16.f16.f32 "
        "{%0,%1,%2,%3}, {%4,%5,%6,%7}, {%8,%9}, {%0,%1,%2,%3};"
        : "+f"(c[0]), "+f"(c[1]), "+f"(c[2]), "+f"(c[3])
        : "r"(a[0]), "r"(a[1]), "r"(a[2]), "r"(a[3]), "r"(b[0]), "r"(b[1]));
}

// ---------------- pack kernel: fp32 -> fp16 (A pre-scaled by 30) ----------------
__global__ void pack_kernel(const float* __restrict__ A, const float* __restrict__ lut,
                            const float* __restrict__ cq, const float* __restrict__ nonid)
{
    const int t = threadIdx.x;
    const int row = blockIdx.x * 4 + (t >> 6);     // 4 rows per block
    const int k0 = (t & 63) * 4;

    const float* src;
    __half* dst;
    float mul = 1.0f;
    if (row < M_TOT) {
        src = A + (size_t)row * K_DIM;
        dst = g_A + (size_t)row * K_DIM;
        mul = SCALE;
    } else {
        const int n = row - M_TOT;
        dst = g_B + (size_t)n * K_DIM;
        if (n < N_LUT)              src = lut   + (size_t)n * K_DIM;
        else if (n < N_LUT + N_CQ)  src = cq    + (size_t)(n - N_LUT) * K_DIM;
        else if (n < N_TOT)         src = nonid + (size_t)(n - N_LUT - N_CQ) * K_DIM;
        else                        src = nullptr;   // zero padding rows
    }

    float4 v = src ? *reinterpret_cast<const float4*>(src + k0)
                   : make_float4(0.f, 0.f, 0.f, 0.f);

    unsigned short h[4];
    h[0] = __half_as_ushort(__float2half_rn(v.x * mul));
    h[1] = __half_as_ushort(__float2half_rn(v.y * mul));
    h[2] = __half_as_ushort(__float2half_rn(v.z * mul));
    h[3] = __half_as_ushort(__float2half_rn(v.w * mul));
    uint2 p;
    p.x = ((u32)h[1] << 16) | h[0];
    p.y = ((u32)h[3] << 16) | h[2];
    *reinterpret_cast<uint2*>(dst + k0) = p;
}

// ---------------- main GEMM: cp.async pipeline + ldmatrix + mma.sync ----------------
__global__ void __launch_bounds__(NTHREADS, 2)
oim_mma_gemm(float* __restrict__ out)
{
    extern __shared__ char smem_raw[];
    u32 base = cvta_smem(smem_raw);
    base = (base + 1023u) & ~1023u;        // 1024-align tile region

    const int tid = threadIdx.x;
    const int lid = tid & 31;
    const int wid = tid >> 5;
    const int wm  = wid & 1;               // 2 warps in M
    const int wn  = wid >> 1;              // 4 warps in N

    const int m0 = blockIdx.y * BM;
    const int n0 = blockIdx.x * BN;

    // ---- producer mapping: each thread copies 4 A + 4 B 16B segments per chunk
    const int r0  = tid >> 3;              // 0..31
    const int seg = tid & 7;               // 16B segment within 128B row

    // ---- ldmatrix lane constants
    const int mat = lid >> 3, rr = lid & 7;
    const int a_row = wm * 64 + ((mat & 1) << 3) + rr;   // + mi*16
    const u32 a_xor = (u32)(a_row & 7);
    const int a_ck  = mat >> 1;                           // 16B chunk within k16
    const int b_row = wn * 32 + ((mat >> 1) << 3) + rr;   // + p*16
    const u32 b_xor = (u32)(b_row & 7);
    const int b_ck  = mat & 1;

    float acc[4][4][4];
    #pragma unroll
    for (int i = 0; i < 4; i++)
        #pragma unroll
        for (int j = 0; j < 4; j++)
            #pragma unroll
            for (int v = 0; v < 4; v++)
                acc[i][j][v] = 0.f;

    // chunk c covers K columns [c*64, c*64+64)
    auto issue_chunk = [&](int c) {
        const int koff = c << 6;
        const u32 stage = base + (u32)(c % STAGES) * STAGE_BYTES;
        const __half* asrc = g_A + (size_t)(m0 + r0) * K_DIM + koff + seg * 8;
        const __half* bsrc = g_B + (size_t)(n0 + r0) * K_DIM + koff + seg * 8;
        #pragma unroll
        for (int j = 0; j < 4; ++j) {
            const u32 rel = (u32)((r0 + j * 32) * 128 + seg * 16);
            const u32 sw  = rel ^ ((rel >> 3) & 0x70u);
            cp_async16(stage + sw,          asrc + (size_t)j * 32 * K_DIM);
            cp_async16(stage + 16384u + sw, bsrc + (size_t)j * 32 * K_DIM);
        }
        asm volatile("cp.async.commit_group;" ::: "memory");
    };

    issue_chunk(0);
    issue_chunk(1);

    #pragma unroll
    for (int q = 0; q < NCHUNK; ++q) {
        if (q < NCHUNK - 1) asm volatile("cp.async.wait_group 1;" ::: "memory");
        else                asm volatile("cp.async.wait_group 0;" ::: "memory");
        __syncthreads();   // chunk q resident; prior reads of recycled stage done

        if (q + 2 < NCHUNK) issue_chunk(q + 2);

        const u32 sA = base + (u32)(q % STAGES) * STAGE_BYTES;
        const u32 sB = sA + 16384u;

        #pragma unroll
        for (int ks = 0; ks < 4; ++ks) {
            u32 af[4][4];
            #pragma unroll
            for (int mi = 0; mi < 4; ++mi) {
                const u32 row  = (u32)(a_row + mi * 16);
                const u32 addr = sA + row * 128u + ((((u32)(ks * 2 + a_ck)) ^ a_xor) << 4);
                ldmatrix4(af[mi], addr);
            }
            u32 bf[4][2];
            #pragma unroll
            for (int p = 0; p < 2; ++p) {
                const u32 row  = (u32)(b_row + p * 16);
                const u32 addr = sB + row * 128u + ((((u32)(ks * 2 + b_ck)) ^ b_xor) << 4);
                u32 t[4];
                ldmatrix4(t, addr);
                bf[p * 2][0] = t[0];     bf[p * 2][1] = t[1];
                bf[p * 2 + 1][0] = t[2]; bf[p * 2 + 1][1] = t[3];
            }
            #pragma unroll
            for (int mi = 0; mi < 4; ++mi)
                #pragma unroll
                for (int ni = 0; ni < 4; ++ni)
                    mma_fp16(acc[mi][ni], af[mi], bf[ni]);
        }
    }

    // ---- epilogue: store float2 pairs (A pre-scaled; even-aligned; N_TOT even)
    const int row_base = m0 + wm * 64 + (lid >> 2);
    const int col_base = n0 + wn * 32 + (lid & 3) * 2;

    #pragma unroll
    for (int mi = 0; mi < 4; ++mi) {
        const int r1 = row_base + mi * 16;
        float* o1 = out + (size_t)r1 * N_TOT;
        float* o2 = out + (size_t)(r1 + 8) * N_TOT;
        #pragma unroll
        for (int ni = 0; ni < 4; ++ni) {
            const int col = col_base + ni * 8;
            if (col < N_TOT) {
                float2 v0, v1;
                v0.x = acc[mi][ni][0];  v0.y = acc[mi][ni][1];
                v1.x = acc[mi][ni][2];  v1.y = acc[mi][ni][3];
                *reinterpret_cast<float2*>(o1 + col) = v0;
                *reinterpret_cast<float2*>(o2 + col) = v1;
            }
        }
    }
}

// ---------------- launch ----------------
extern "C" void kernel_launch(void* const* d_in, const int* in_sizes, int n_in,
                              void* d_out, int out_size)
{
    // metadata order: inputs, non_id_feat, lut, cq, first_pos, second_pos, targets, half, header
    const float* inputs = (const float*)d_in[0];
    const float* nonid  = (const float*)d_in[1];
    const float* lut    = (const float*)d_in[2];
    const float* cq     = (const float*)d_in[3];
    float* out = (float*)d_out;

    pack_kernel<<<(M_TOT + N_PAD) / 4, 256>>>(inputs, lut, cq, nonid);

    cudaFuncSetAttribute(oim_mma_gemm, cudaFuncAttributeMaxDynamicSharedMemorySize, SMEM_BYTES);
    dim3 grid((N_TOT + BN - 1) / BN, M_TOT / BM);   // 85 x 16
    oim_mma_gemm<<<grid, NTHREADS, SMEM_BYTES>>>(out);
}